// round 12
// baseline (speedup 1.0000x reference)
#include <cuda_runtime.h>
#include <cstdint>

#define TOKENS     256
#define IN_F       4096
#define OUT_F      4096
#define NUM_CHUNKS 16384
#define CHUNK_SIZE 1024
#define D_ALPHA    64
#define HIDDEN     256

#define Y_SPLITS   8    // K=1024 -> 8 x 128
#define O_SPLITS   4    // K=1024 -> 4 x 256

// Scratch (static device globals: allocation-free per harness rules)
__device__ float g_h[NUM_CHUNKS * HIDDEN];               // 16 MB; == H2 (4096,1024)
__device__ float g_w2t[HIDDEN * CHUNK_SIZE];             // 1 MB: w2^T (256, 1024)
__device__ float g_y[TOKENS * CHUNK_SIZE];               // 1 MB: y (256, 1024)
__device__ float g_S[TOKENS];                            // per-token b2 contribution
__device__ float g_ypart[Y_SPLITS][TOKENS * CHUNK_SIZE]; // 8 MB split-K partials for y
__device__ float g_opart[O_SPLITS][TOKENS * OUT_F];      // 16 MB split-K partials for out
__device__ int   g_ycnt[32];                             // per-tile arrival counters (y)
__device__ int   g_ocnt[128];                            // per-tile arrival counters (out)

// ---------------------------------------------------------------------------
// helpers
// ---------------------------------------------------------------------------
__device__ __forceinline__ uint32_t f2tf32(float x) {
    uint32_t r;
    asm("cvt.rna.tf32.f32 %0, %1;" : "=r"(r) : "f"(x));
    return r;
}

__device__ __forceinline__ void mma_tf32(float d[4], const uint32_t a[4],
                                         const uint32_t b[2], const float c[4]) {
    asm volatile(
        "mma.sync.aligned.m16n8k8.row.col.f32.tf32.tf32.f32 "
        "{%0,%1,%2,%3}, {%4,%5,%6,%7}, {%8,%9}, {%10,%11,%12,%13};\n"
        : "=f"(d[0]), "=f"(d[1]), "=f"(d[2]), "=f"(d[3])
        : "r"(a[0]), "r"(a[1]), "r"(a[2]), "r"(a[3]),
          "r"(b[0]), "r"(b[1]),
          "f"(c[0]), "f"(c[1]), "f"(c[2]), "f"(c[3]));
}

__device__ __forceinline__ void cp_async16(void* dst, const void* src) {
    uint32_t s = (uint32_t)__cvta_generic_to_shared(dst);
    asm volatile("cp.async.cg.shared.global [%0], [%1], 16;\n" :: "r"(s), "l"(src));
}
__device__ __forceinline__ void cp_commit() {
    asm volatile("cp.async.commit_group;\n" ::: "memory");
}
__device__ __forceinline__ void cp_wait0() {
    asm volatile("cp.async.wait_group 0;\n" ::: "memory");
}

#define EPI_NONE 0
#define EPI_GELU 2

__device__ __forceinline__ float gelu_exact(float v) {
    return 0.5f * v * (1.0f + erff(v * 0.70710678118654752f));
}

// ---------------------------------------------------------------------------
// tf32 GEMM tile: C[128,64] (+epilogue) = A[128,K] @ B[64,K]^T
// 128 threads (4 warps of 64x32), BK=16, double-buffered cp.async,
// smem rows padded to 20 floats (conflict-free fragment LDS). R9-proven config.
// ---------------------------------------------------------------------------
template <int KT, int LDA, int LDB, int LDC, int EPI>
__device__ __forceinline__ void gemm_body(const float* __restrict__ A,
                                          const float* __restrict__ B,
                                          const float* __restrict__ bias,
                                          float* __restrict__ C) {
    constexpr int BK = 16;
    constexpr int PAD = 20;

    __shared__ __align__(16) float As[2][128 * PAD];
    __shared__ __align__(16) float Bs[2][64 * PAD];

    const int tid  = threadIdx.x;
    const int bm   = blockIdx.y * 128;
    const int bn   = blockIdx.x * 64;
    const int lane = tid & 31;
    const int wid  = tid >> 5;
    const int warpM = (wid & 1) * 64;
    const int warpN = (wid >> 1) * 32;
    const int g = lane >> 2;
    const int t = lane & 3;

    const int lrow = tid >> 2;        // 0..31
    const int lcol = (tid & 3) * 4;   // 0,4,8,12

    float acc[4][4][4];
    #pragma unroll
    for (int m = 0; m < 4; m++)
        #pragma unroll
        for (int n = 0; n < 4; n++)
            #pragma unroll
            for (int i = 0; i < 4; i++)
                acc[m][n][i] = 0.0f;

    auto load_tile = [&](int kt, int buf) {
        const float* Ag = A + (size_t)(bm + lrow) * LDA + kt * BK + lcol;
        float* Ad = &As[buf][lrow * PAD + lcol];
        #pragma unroll
        for (int i = 0; i < 4; i++)
            cp_async16(Ad + i * 32 * PAD, Ag + (size_t)i * 32 * LDA);
        const float* Bg = B + (size_t)(bn + lrow) * LDB + kt * BK + lcol;
        float* Bd = &Bs[buf][lrow * PAD + lcol];
        #pragma unroll
        for (int i = 0; i < 2; i++)
            cp_async16(Bd + i * 32 * PAD, Bg + (size_t)i * 32 * LDB);
        cp_commit();
    };

    load_tile(0, 0);

    for (int kt = 0; kt < KT; kt++) {
        cp_wait0();
        __syncthreads();
        if (kt + 1 < KT) load_tile(kt + 1, (kt + 1) & 1);

        const float* Asb = As[kt & 1];
        const float* Bsb = Bs[kt & 1];

        #pragma unroll
        for (int k0 = 0; k0 < BK; k0 += 8) {
            uint32_t af[4][4];
            uint32_t bf[4][2];
            #pragma unroll
            for (int m = 0; m < 4; m++) {
                const float* p = Asb + (warpM + m * 16 + g) * PAD + k0 + t;
                af[m][0] = f2tf32(p[0]);
                af[m][1] = f2tf32(p[8 * PAD]);
                af[m][2] = f2tf32(p[4]);
                af[m][3] = f2tf32(p[8 * PAD + 4]);
            }
            #pragma unroll
            for (int n = 0; n < 4; n++) {
                const float* p = Bsb + (warpN + n * 8 + g) * PAD + k0 + t;
                bf[n][0] = f2tf32(p[0]);
                bf[n][1] = f2tf32(p[4]);
            }
            #pragma unroll
            for (int m = 0; m < 4; m++)
                #pragma unroll
                for (int n = 0; n < 4; n++)
                    mma_tf32(acc[m][n], af[m], bf[n], acc[m][n]);
        }
        __syncthreads();
    }

    // epilogue
    #pragma unroll
    for (int m = 0; m < 4; m++) {
        const int r0 = bm + warpM + m * 16 + g;
        #pragma unroll
        for (int n = 0; n < 4; n++) {
            const int c0 = bn + warpN + n * 8 + 2 * t;
            float bv0 = 0.0f, bv1 = 0.0f;
            if (EPI == EPI_GELU) { bv0 = bias[c0]; bv1 = bias[c0 + 1]; }
            float v00 = acc[m][n][0] + bv0;
            float v01 = acc[m][n][1] + bv1;
            float v10 = acc[m][n][2] + bv0;
            float v11 = acc[m][n][3] + bv1;
            if (EPI == EPI_GELU) {
                v00 = gelu_exact(v00); v01 = gelu_exact(v01);
                v10 = gelu_exact(v10); v11 = gelu_exact(v11);
            }
            C[(size_t)r0 * LDC + c0]           = v00;
            C[(size_t)r0 * LDC + c0 + 1]       = v01;
            C[(size_t)(r0 + 8) * LDC + c0]     = v10;
            C[(size_t)(r0 + 8) * LDC + c0 + 1] = v11;
        }
    }
}

// Last-CTA-reduces handshake. Returns true if this CTA must do the reduction.
__device__ __forceinline__ bool arrive_last(int* cnt, int nsplits) {
    __shared__ int s_last;
    __threadfence();                 // make this thread's partial stores visible
    __syncthreads();
    if (threadIdx.x == 0) {
        int old = atomicAdd(cnt, 1);
        s_last = (old == nsplits - 1) ? 1 : 0;
    }
    __syncthreads();
    bool last = (s_last != 0);
    if (last) __threadfence();       // acquire: order peers' stores before our reads
    return last;
}

// ---------------------------------------------------------------------------
// Kernel A (prep): blocks [0,256) transpose w2; blocks [256,512) S[t].
// Block 0 additionally zeroes the split-K arrival counters.
// ---------------------------------------------------------------------------
__global__ __launch_bounds__(256) void prep_kernel(const float* __restrict__ w2,
                                                   const float* __restrict__ x,
                                                   const float* __restrict__ b2) {
    const int b = blockIdx.x;
    const int tid = threadIdx.x;
    if (b == 0) {
        if (tid < 32)  g_ycnt[tid] = 0;
        if (tid < 128) g_ocnt[tid] = 0;
    }
    if (b < 256) {
        __shared__ float tile[32][33];
        const int m0 = (b & 7) * 32;
        const int j0 = (b >> 3) * 32;
        const int tx = tid & 31;
        const int ty = tid >> 5;
        #pragma unroll
        for (int i = 0; i < 32; i += 8)
            tile[ty + i][tx] = w2[(size_t)(j0 + ty + i) * HIDDEN + m0 + tx];
        __syncthreads();
        #pragma unroll
        for (int i = 0; i < 32; i += 8)
            g_w2t[(size_t)(m0 + ty + i) * CHUNK_SIZE + j0 + tx] = tile[tx][ty + i];
    } else {
        const int t = b - 256;
        const float* xr = x + (size_t)t * IN_F;
        float a = 0.0f;
        #pragma unroll
        for (int j = tid; j < CHUNK_SIZE; j += 256) {
            float xs = xr[j] + xr[j + 1024] + xr[j + 2048] + xr[j + 3072];
            a = fmaf(b2[j], xs, a);
        }
        #pragma unroll
        for (int off = 16; off > 0; off >>= 1)
            a += __shfl_xor_sync(0xffffffffu, a, off);
        __shared__ float sred[8];
        if ((tid & 31) == 0) sred[tid >> 5] = a;
        __syncthreads();
        if (tid == 0) {
            float s = 0.0f;
            #pragma unroll
            for (int i = 0; i < 8; i++) s += sred[i];
            g_S[t] = s;
        }
    }
}

// ---------------------------------------------------------------------------
// Kernel B: h = gelu(codebook @ w1^T + b1)   M=16384, N=256, K=64
// ---------------------------------------------------------------------------
__global__ __launch_bounds__(128) void h_gemm_kernel(const float* __restrict__ cb,
                                                     const float* __restrict__ w1,
                                                     const float* __restrict__ b1) {
    gemm_body<D_ALPHA / 16, D_ALPHA, D_ALPHA, HIDDEN, EPI_GELU>(cb, w1, b1, g_h);
}

// ---------------------------------------------------------------------------
// Kernel C: split-K y partials + fused last-CTA reduction into g_y.
// z: c = z>>3 (0..3), s = z&7. K slice [s*128, (s+1)*128).
// ---------------------------------------------------------------------------
__global__ __launch_bounds__(128) void y_gemm_split_kernel(const float* __restrict__ x) {
    const int z = blockIdx.z;
    const int c = z >> 3;
    const int s = z & (Y_SPLITS - 1);
    const float* A = x + c * CHUNK_SIZE + s * (CHUNK_SIZE / Y_SPLITS);
    const float* B = g_w2t + s * (CHUNK_SIZE / Y_SPLITS);
    float* C = g_ypart[s] + c * HIDDEN;
    gemm_body<(CHUNK_SIZE / Y_SPLITS) / 16, IN_F, CHUNK_SIZE, CHUNK_SIZE, EPI_NONE>(
        A, B, nullptr, C);

    const int tile = blockIdx.x + 4 * blockIdx.y + 8 * c;
    if (arrive_last(&g_ycnt[tile], Y_SPLITS)) {
        // reduce rows [bm, bm+128) x cols [c*256+bn, +64) in fixed s order
        const int r = blockIdx.y * 128 + threadIdx.x;          // one row per thread
        const int col4 = c * 64 + blockIdx.x * 16;             // f4 col base (of 256)
        const size_t base = (size_t)r * (CHUNK_SIZE / 4) + col4;
        #pragma unroll
        for (int j = 0; j < 16; j++) {
            float4 a = ((const float4*)g_ypart[0])[base + j];
            #pragma unroll
            for (int ss = 1; ss < Y_SPLITS; ss++) {
                float4 b = ((const float4*)g_ypart[ss])[base + j];
                a.x += b.x; a.y += b.y; a.z += b.z; a.w += b.w;
            }
            ((float4*)g_y)[base + j] = a;
        }
    }
}

// ---------------------------------------------------------------------------
// Kernel D: split-K out partials + fused last-CTA reduction (+bias+S) into out.
// ---------------------------------------------------------------------------
__global__ __launch_bounds__(128) void out_gemm_split_kernel(const float* __restrict__ bias,
                                                             float* __restrict__ out) {
    const int s = blockIdx.z;
    const float* A = g_y + s * (CHUNK_SIZE / O_SPLITS);
    const float* B = g_h + s * (CHUNK_SIZE / O_SPLITS);
    float* C = g_opart[s];
    gemm_body<(CHUNK_SIZE / O_SPLITS) / 16, CHUNK_SIZE, CHUNK_SIZE, OUT_F, EPI_NONE>(
        A, B, nullptr, C);

    const int tile = blockIdx.x + 64 * blockIdx.y;
    if (arrive_last(&g_ocnt[tile], O_SPLITS)) {
        const int r = blockIdx.y * 128 + threadIdx.x;          // one row per thread
        const int col4 = blockIdx.x * 16;                      // f4 col base (of 1024)
        const size_t base = (size_t)r * (OUT_F / 4) + col4;
        const float sv = g_S[r];
        #pragma unroll
        for (int j = 0; j < 16; j++) {
            float4 a = ((const float4*)g_opart[0])[base + j];
            #pragma unroll
            for (int ss = 1; ss < O_SPLITS; ss++) {
                float4 b = ((const float4*)g_opart[ss])[base + j];
                a.x += b.x; a.y += b.y; a.z += b.z; a.w += b.w;
            }
            const float4 bv = ((const float4*)bias)[col4 + j];
            a.x += bv.x + sv; a.y += bv.y + sv; a.z += bv.z + sv; a.w += bv.w + sv;
            ((float4*)out)[base + j] = a;
        }
    }
}

// ---------------------------------------------------------------------------
extern "C" void kernel_launch(void* const* d_in, const int* in_sizes, int n_in,
                              void* d_out, int out_size) {
    const float* x    = (const float*)d_in[0];  // (256, 4096)
    const float* cb   = (const float*)d_in[1];  // (16384, 64)
    const float* w1   = (const float*)d_in[2];  // (256, 64)
    const float* b1   = (const float*)d_in[3];  // (256,)
    const float* w2   = (const float*)d_in[4];  // (1024, 256)
    const float* b2   = (const float*)d_in[5];  // (1024,)
    const float* bias = (const float*)d_in[6];  // (4096,)
    float* out = (float*)d_out;                 // (256, 4096)

    prep_kernel<<<512, 256>>>(w2, x, b2);

    h_gemm_kernel<<<dim3(HIDDEN / 64, NUM_CHUNKS / 128), 128>>>(cb, w1, b1);

    // y split-K: grid (4 n-tiles, 2 m-tiles, 4c * 8 splits) = 256 CTAs
    y_gemm_split_kernel<<<dim3(HIDDEN / 64, TOKENS / 128, 4 * Y_SPLITS), 128>>>(x);

    // out split-K: grid (64, 2, 4) = 512 CTAs
    out_gemm_split_kernel<<<dim3(OUT_F / 64, TOKENS / 128, O_SPLITS), 128>>>(bias, out);
}

// round 13
// speedup vs baseline: 1.6027x; 1.6027x over previous
#include <cuda_runtime.h>
#include <cstdint>

#define TOKENS     256
#define IN_F       4096
#define OUT_F      4096
#define NUM_CHUNKS 16384
#define CHUNK_SIZE 1024
#define D_ALPHA    64
#define HIDDEN     256

#define Y_SPLITS   8    // K=1024 -> 8 x 128
#define O_SPLITS   4    // K=1024 -> 4 x 256

#define GPAD 20
#define GEMM_SMEM_BYTES ((2 * 128 * GPAD + 2 * 64 * GPAD) * 4)   // 30720

// Scratch (static device globals: allocation-free per harness rules)
__device__ float g_h[NUM_CHUNKS * HIDDEN];               // 16 MB; == H2 (4096,1024)
__device__ float g_w2t[HIDDEN * CHUNK_SIZE];             // 1 MB: w2^T (256, 1024)
__device__ float g_y[TOKENS * CHUNK_SIZE];               // 1 MB: y (256, 1024)
__device__ float g_S[TOKENS];                            // per-token b2 contribution
__device__ float g_ypart[Y_SPLITS][TOKENS * CHUNK_SIZE]; // 8 MB split-K partials for y
__device__ float g_opart[O_SPLITS][TOKENS * OUT_F];      // 16 MB split-K partials for out

// ---------------------------------------------------------------------------
// helpers
// ---------------------------------------------------------------------------
__device__ __forceinline__ uint32_t f2tf32(float x) {
    uint32_t r;
    asm("cvt.rna.tf32.f32 %0, %1;" : "=r"(r) : "f"(x));
    return r;
}

__device__ __forceinline__ void mma_tf32(float d[4], const uint32_t a[4],
                                         const uint32_t b[2], const float c[4]) {
    asm volatile(
        "mma.sync.aligned.m16n8k8.row.col.f32.tf32.tf32.f32 "
        "{%0,%1,%2,%3}, {%4,%5,%6,%7}, {%8,%9}, {%10,%11,%12,%13};\n"
        : "=f"(d[0]), "=f"(d[1]), "=f"(d[2]), "=f"(d[3])
        : "r"(a[0]), "r"(a[1]), "r"(a[2]), "r"(a[3]),
          "r"(b[0]), "r"(b[1]),
          "f"(c[0]), "f"(c[1]), "f"(c[2]), "f"(c[3]));
}

__device__ __forceinline__ void cp_async16(void* dst, const void* src) {
    uint32_t s = (uint32_t)__cvta_generic_to_shared(dst);
    asm volatile("cp.async.cg.shared.global [%0], [%1], 16;\n" :: "r"(s), "l"(src));
}
__device__ __forceinline__ void cp_commit() {
    asm volatile("cp.async.commit_group;\n" ::: "memory");
}
__device__ __forceinline__ void cp_wait0() {
    asm volatile("cp.async.wait_group 0;\n" ::: "memory");
}

#define EPI_NONE 0
#define EPI_GELU 2

__device__ __forceinline__ float gelu_exact(float v) {
    return 0.5f * v * (1.0f + erff(v * 0.70710678118654752f));
}

// ---------------------------------------------------------------------------
// tf32 GEMM tile: C[bm:bm+128, bn:bn+64] (+epilogue) = A[128,K] @ B[64,K]^T
// 128 threads (4 warps of 64x32), BK=16, double-buffered cp.async,
// smem rows padded to GPAD=20 floats. Dynamic smem arena (shared across
// template instantiations living in the same kernel).
// ---------------------------------------------------------------------------
template <int KT, int LDA, int LDB, int LDC, int EPI>
__device__ __forceinline__ void gemm_body(const float* __restrict__ A,
                                          const float* __restrict__ B,
                                          const float* __restrict__ bias,
                                          float* __restrict__ C,
                                          int bm, int bn) {
    constexpr int BK = 16;
    constexpr int PAD = GPAD;

    extern __shared__ float smem_arena[];
    float* AsBuf = smem_arena;                     // 2 * 128*PAD
    float* BsBuf = smem_arena + 2 * 128 * PAD;     // 2 * 64*PAD

    const int tid  = threadIdx.x;
    const int lane = tid & 31;
    const int wid  = tid >> 5;
    const int warpM = (wid & 1) * 64;
    const int warpN = (wid >> 1) * 32;
    const int g = lane >> 2;
    const int t = lane & 3;

    const int lrow = tid >> 2;        // 0..31
    const int lcol = (tid & 3) * 4;   // 0,4,8,12

    float acc[4][4][4];
    #pragma unroll
    for (int m = 0; m < 4; m++)
        #pragma unroll
        for (int n = 0; n < 4; n++)
            #pragma unroll
            for (int i = 0; i < 4; i++)
                acc[m][n][i] = 0.0f;

    auto load_tile = [&](int kt, int buf) {
        const float* Ag = A + (size_t)(bm + lrow) * LDA + kt * BK + lcol;
        float* Ad = AsBuf + buf * 128 * PAD + lrow * PAD + lcol;
        #pragma unroll
        for (int i = 0; i < 4; i++)
            cp_async16(Ad + i * 32 * PAD, Ag + (size_t)i * 32 * LDA);
        const float* Bg = B + (size_t)(bn + lrow) * LDB + kt * BK + lcol;
        float* Bd = BsBuf + buf * 64 * PAD + lrow * PAD + lcol;
        #pragma unroll
        for (int i = 0; i < 2; i++)
            cp_async16(Bd + i * 32 * PAD, Bg + (size_t)i * 32 * LDB);
        cp_commit();
    };

    load_tile(0, 0);

    for (int kt = 0; kt < KT; kt++) {
        cp_wait0();
        __syncthreads();
        if (kt + 1 < KT) load_tile(kt + 1, (kt + 1) & 1);

        const float* Asb = AsBuf + (kt & 1) * 128 * PAD;
        const float* Bsb = BsBuf + (kt & 1) * 64 * PAD;

        #pragma unroll
        for (int k0 = 0; k0 < BK; k0 += 8) {
            uint32_t af[4][4];
            uint32_t bf[4][2];
            #pragma unroll
            for (int m = 0; m < 4; m++) {
                const float* p = Asb + (warpM + m * 16 + g) * PAD + k0 + t;
                af[m][0] = f2tf32(p[0]);
                af[m][1] = f2tf32(p[8 * PAD]);
                af[m][2] = f2tf32(p[4]);
                af[m][3] = f2tf32(p[8 * PAD + 4]);
            }
            #pragma unroll
            for (int n = 0; n < 4; n++) {
                const float* p = Bsb + (warpN + n * 8 + g) * PAD + k0 + t;
                bf[n][0] = f2tf32(p[0]);
                bf[n][1] = f2tf32(p[4]);
            }
            #pragma unroll
            for (int m = 0; m < 4; m++)
                #pragma unroll
                for (int n = 0; n < 4; n++)
                    mma_tf32(acc[m][n], af[m], bf[n], acc[m][n]);
        }
        __syncthreads();
    }

    // epilogue
    #pragma unroll
    for (int m = 0; m < 4; m++) {
        const int r0 = bm + warpM + m * 16 + g;
        #pragma unroll
        for (int n = 0; n < 4; n++) {
            const int c0 = bn + warpN + n * 8 + 2 * t;
            float bv0 = 0.0f, bv1 = 0.0f;
            if (EPI == EPI_GELU) { bv0 = bias[c0]; bv1 = bias[c0 + 1]; }
            float v00 = acc[m][n][0] + bv0;
            float v01 = acc[m][n][1] + bv1;
            float v10 = acc[m][n][2] + bv0;
            float v11 = acc[m][n][3] + bv1;
            if (EPI == EPI_GELU) {
                v00 = gelu_exact(v00); v01 = gelu_exact(v01);
                v10 = gelu_exact(v10); v11 = gelu_exact(v11);
            }
            C[(size_t)r0 * LDC + c0]           = v00;
            C[(size_t)r0 * LDC + c0 + 1]       = v01;
            C[(size_t)(r0 + 8) * LDC + c0]     = v10;
            C[(size_t)(r0 + 8) * LDC + c0 + 1] = v11;
        }
    }
}

// ---------------------------------------------------------------------------
// Kernel A (prep): blocks [0,256) transpose w2 -> g_w2t; blocks [256,512) S[t].
// ---------------------------------------------------------------------------
__global__ __launch_bounds__(256) void prep_kernel(const float* __restrict__ w2,
                                                   const float* __restrict__ x,
                                                   const float* __restrict__ b2) {
    const int b = blockIdx.x;
    const int tid = threadIdx.x;
    if (b < 256) {
        __shared__ float tile[32][33];
        const int m0 = (b & 7) * 32;
        const int j0 = (b >> 3) * 32;
        const int tx = tid & 31;
        const int ty = tid >> 5;
        #pragma unroll
        for (int i = 0; i < 32; i += 8)
            tile[ty + i][tx] = w2[(size_t)(j0 + ty + i) * HIDDEN + m0 + tx];
        __syncthreads();
        #pragma unroll
        for (int i = 0; i < 32; i += 8)
            g_w2t[(size_t)(m0 + ty + i) * CHUNK_SIZE + j0 + tx] = tile[tx][ty + i];
    } else {
        const int t = b - 256;
        const float* xr = x + (size_t)t * IN_F;
        float a = 0.0f;
        #pragma unroll
        for (int j = tid; j < CHUNK_SIZE; j += 256) {
            float xs = xr[j] + xr[j + 1024] + xr[j + 2048] + xr[j + 3072];
            a = fmaf(b2[j], xs, a);
        }
        #pragma unroll
        for (int off = 16; off > 0; off >>= 1)
            a += __shfl_xor_sync(0xffffffffu, a, off);
        __shared__ float sred[8];
        if ((tid & 31) == 0) sred[tid >> 5] = a;
        __syncthreads();
        if (tid == 0) {
            float s = 0.0f;
            #pragma unroll
            for (int i = 0; i < 8; i++) s += sred[i];
            g_S[t] = s;
        }
    }
}

// ---------------------------------------------------------------------------
// Kernel B (fused): blocks [0,256) = y split-K tiles (critical path first),
//                   blocks [256,768) = h GEMM tiles.
// ---------------------------------------------------------------------------
__global__ __launch_bounds__(128) void hy_fused_kernel(const float* __restrict__ x,
                                                       const float* __restrict__ cb,
                                                       const float* __restrict__ w1,
                                                       const float* __restrict__ b1) {
    const int b = blockIdx.x;
    if (b < 256) {
        // y split-K partial: decode (n, m, z) from b; z -> (c, s)
        const int n = b & 3;
        const int m = (b >> 2) & 1;
        const int z = b >> 3;            // 0..31
        const int c = z >> 3;            // 0..3
        const int s = z & (Y_SPLITS - 1);
        const float* A = x + c * CHUNK_SIZE + s * (CHUNK_SIZE / Y_SPLITS);
        const float* B = g_w2t + s * (CHUNK_SIZE / Y_SPLITS);
        float* C = g_ypart[s] + c * HIDDEN;
        gemm_body<(CHUNK_SIZE / Y_SPLITS) / 16, IN_F, CHUNK_SIZE, CHUNK_SIZE, EPI_NONE>(
            A, B, nullptr, C, m * 128, n * 64);
    } else {
        // h = gelu(cb @ w1^T + b1): tile hb in grid (4 n, 128 m)
        const int hb = b - 256;
        const int n = hb & 3;
        const int m = hb >> 2;
        gemm_body<D_ALPHA / 16, D_ALPHA, D_ALPHA, HIDDEN, EPI_GELU>(
            cb, w1, b1, g_h, m * 128, n * 64);
    }
}

// ---------------------------------------------------------------------------
// Kernel C: g_y = sum_s g_ypart[s]  (128 blocks x 256 thr, 2 float4/thread)
// ---------------------------------------------------------------------------
__global__ __launch_bounds__(256) void reduce_y_kernel() {
    const int idx = blockIdx.x * 256 + threadIdx.x;       // 0..32767
    const int idx2 = idx + 32768;
    float4 a = ((const float4*)g_ypart[0])[idx];
    float4 a2 = ((const float4*)g_ypart[0])[idx2];
    #pragma unroll
    for (int s = 1; s < Y_SPLITS; s++) {
        float4 b = ((const float4*)g_ypart[s])[idx];
        float4 b2 = ((const float4*)g_ypart[s])[idx2];
        a.x += b.x; a.y += b.y; a.z += b.z; a.w += b.w;
        a2.x += b2.x; a2.y += b2.y; a2.z += b2.z; a2.w += b2.w;
    }
    ((float4*)g_y)[idx] = a;
    ((float4*)g_y)[idx2] = a2;
}

// ---------------------------------------------------------------------------
// Kernel D: split-K out partials: out = g_y @ H2^T, H2 = g_h as (4096,1024)
// ---------------------------------------------------------------------------
__global__ __launch_bounds__(128) void out_gemm_split_kernel() {
    const int s = blockIdx.z;
    const float* A = g_y + s * (CHUNK_SIZE / O_SPLITS);
    const float* B = g_h + s * (CHUNK_SIZE / O_SPLITS);
    float* C = g_opart[s];
    gemm_body<(CHUNK_SIZE / O_SPLITS) / 16, CHUNK_SIZE, CHUNK_SIZE, OUT_F, EPI_NONE>(
        A, B, nullptr, C, blockIdx.y * 128, blockIdx.x * 64);
}

// ---------------------------------------------------------------------------
// Kernel E: out = sum_s g_opart[s] + bias[o] + S[t]
//           256 blocks x 256 thr, 4 float4/thread (stride 65536)
// ---------------------------------------------------------------------------
__global__ __launch_bounds__(256) void reduce_out_kernel(const float* __restrict__ bias,
                                                         float* __restrict__ out) {
    const int base = blockIdx.x * 256 + threadIdx.x;      // 0..65535
    #pragma unroll
    for (int q = 0; q < 4; q++) {
        const int idx = base + q * 65536;                 // f4 index over 262144
        const int t  = idx >> 10;
        const int o4 = idx & 1023;
        float4 a = ((const float4*)g_opart[0])[idx];
        #pragma unroll
        for (int s = 1; s < O_SPLITS; s++) {
            float4 b = ((const float4*)g_opart[s])[idx];
            a.x += b.x; a.y += b.y; a.z += b.z; a.w += b.w;
        }
        const float4 bv = ((const float4*)bias)[o4];
        const float sv = g_S[t];
        a.x += bv.x + sv; a.y += bv.y + sv; a.z += bv.z + sv; a.w += bv.w + sv;
        ((float4*)out)[idx] = a;
    }
}

// ---------------------------------------------------------------------------
extern "C" void kernel_launch(void* const* d_in, const int* in_sizes, int n_in,
                              void* d_out, int out_size) {
    const float* x    = (const float*)d_in[0];  // (256, 4096)
    const float* cb   = (const float*)d_in[1];  // (16384, 64)
    const float* w1   = (const float*)d_in[2];  // (256, 64)
    const float* b1   = (const float*)d_in[3];  // (256,)
    const float* w2   = (const float*)d_in[4];  // (1024, 256)
    const float* b2   = (const float*)d_in[5];  // (1024,)
    const float* bias = (const float*)d_in[6];  // (4096,)
    float* out = (float*)d_out;                 // (256, 4096)

    prep_kernel<<<512, 256>>>(w2, x, b2);

    // fused h + y split-K: 768 CTAs, y tiles first
    hy_fused_kernel<<<768, 128, GEMM_SMEM_BYTES>>>(x, cb, w1, b1);

    reduce_y_kernel<<<128, 256>>>();

    // out split-K: grid (64 n, 2 m, 4 s) = 512 CTAs
    out_gemm_split_kernel<<<dim3(OUT_F / 64, TOKENS / 128, O_SPLITS), 128,
                            GEMM_SMEM_BYTES>>>();

    reduce_out_kernel<<<256, 256>>>(bias, out);
}